// round 7
// baseline (speedup 1.0000x reference)
#include <cuda_runtime.h>
#include <math.h>

// Problem constants (fixed by the reference)
#define B_DIM 2
#define L_DIM 2048
#define V_DIM 32001
#define ROWS (B_DIM * L_DIM)                       // 4096
#define REV_FLOATS (131076096LL)                   // ROWS * V_DIM, divisible by 8
#define N8 (REV_FLOATS / 8)                        // 16384512 32-byte units

#define G_LOGIC 16                                 // logic blocks (4096 threads)
#define G_FILL 4096                                // fill blocks
#define G_TOTAL (G_LOGIC + G_FILL)                 // 4112
#define FILL_CHUNK ((N8 + G_FILL - 1) / G_FILL)    // 4001 F8 per block

struct alignas(32) F8 { float4 a, b; };

// Cross-block state. All of it is returned to 0 by the epilogue block at the
// end of EVERY launch, so graph replays are deterministic.
__device__ int g_done = 0;         // block completion counter
__device__ int g_cnt = 0;          // masked-row worklist size
__device__ int g_rows[ROWS];

__device__ __forceinline__ float gumbel_noise(float u) {
    const float GEPS = 1e-6f;
    return GEPS - logf(GEPS + (1.0f - GEPS) * u);
}

// Single launch:
//   blocks [0, G_LOGIC)          : row logic (x_new for all rows; gumbel sample
//                                  for masked rows in registers/smem; masked
//                                  rows appended to g_rows worklist)
//   blocks [G_LOGIC, G_TOTAL)    : flat 32B-aligned zero fill of rev
//   last block to finish         : epilogue — all fill stores are complete, so
//                                  it writes rev rows for masked rows (worklist
//                                  is empty in practice) and resets counters.
__global__ __launch_bounds__(256, 8)
void fused_kernel(const float* __restrict__ outp,   // [B,L,V]
                  const int* __restrict__ xt,       // [B,L]
                  const float* __restrict__ t,      // [B]
                  const float* __restrict__ step_p, // [1]
                  const float* __restrict__ u,      // [B,L,V]
                  float* __restrict__ x_new,        // [B*L]
                  float* __restrict__ rev)          // [B,L,V]
{
    const int tid = threadIdx.x;
    const int mask_tok = V_DIM - 1;
    const float EPS = 1e-3f;

    __shared__ int s_count;
    __shared__ int s_rows[256];
    __shared__ float s_sum[256];
    __shared__ float s_val[256];
    __shared__ int   s_idx[256];

    if (blockIdx.x >= G_LOGIC) {
        // ---- flat fill: contiguous ~128KB chunk per block, 32B stores ----
        const long long fb = blockIdx.x - G_LOGIC;
        long long base = fb * FILL_CHUNK;
        long long end  = base + FILL_CHUNK;
        if (end > N8) end = N8;
        F8 z; z.a = make_float4(0.f, 0.f, 0.f, 0.f); z.b = z.a;
        F8* __restrict__ p = (F8*)rev;
        for (long long i = base + tid; i < end; i += 256) p[i] = z;
    } else {
        // ---- row logic: thread-per-row ----
        const int row = blockIdx.x * 256 + tid;   // 0..4095
        if (tid == 0) s_count = 0;
        __syncthreads();

        int x = xt[row];
        if (x == -1) x = mask_tok;

        if (x != mask_tok) {
            // rev row is exactly zero; argmax is deterministically x.
            x_new[row] = (float)x;
        } else {
            int slot = atomicAdd(&s_count, 1);
            s_rows[slot] = row;
            int gslot = atomicAdd(&g_cnt, 1);      // rev-row write deferred
            g_rows[gslot] = row;
        }
        __syncthreads();

        const int cnt = s_count;
        if (cnt > 0) {
            // cooperative gumbel sample for masked rows (no rev writes here)
            const float step = *step_p;
            for (int m = 0; m < cnt; m++) {
                const int mrow = s_rows[m];
                const int b = mrow / L_DIM;
                const float sigma = (1.0f - EPS) / (1.0f - (1.0f - EPS) * t[b]);
                const float* __restrict__ orow = outp + (long long)mrow * V_DIM;
                const float* __restrict__ urow = u    + (long long)mrow * V_DIM;

                float sum = 0.0f;
                float best_v = -INFINITY;
                int   best_i = V_DIM;
                for (int v = tid; v < V_DIM; v += 256) {
                    if (v == mask_tok) continue;
                    float s = expf(orow[v]);
                    sum += s;
                    float r = sigma * s;
                    float g = gumbel_noise(urow[v]);
                    float ratio = (step * r) / g;
                    if (ratio > best_v || (ratio == best_v && v < best_i)) {
                        best_v = ratio;
                        best_i = v;
                    }
                }
                s_sum[tid] = sum;
                s_val[tid] = best_v;
                s_idx[tid] = best_i;
                __syncthreads();
                for (int off = 128; off > 0; off >>= 1) {
                    if (tid < off) {
                        s_sum[tid] += s_sum[tid + off];
                        float ov = s_val[tid + off];
                        int   oi = s_idx[tid + off];
                        if (ov > s_val[tid] ||
                            (ov == s_val[tid] && oi < s_idx[tid])) {
                            s_val[tid] = ov;
                            s_idx[tid] = oi;
                        }
                    }
                    __syncthreads();
                }
                if (tid == 0) {
                    float rd = sigma * (-s_sum[0]);        // diagonal rev_rate
                    float prob = 1.0f + step * rd;         // oh=1 at diagonal
                    float g = gumbel_noise(urow[mask_tok]);
                    float ratio = prob / g;
                    int res = s_idx[0];
                    if (ratio > s_val[0]) res = mask_tok;  // tie -> off-diag
                    x_new[mrow] = (res == mask_tok) ? -1.0f : (float)res;
                }
                __syncthreads();
            }
        }
    }

    // ---- completion protocol: last block runs the epilogue ----
    __threadfence();                   // make this block's stores visible
    __shared__ int s_old;
    if (tid == 0) s_old = atomicAdd(&g_done, 1);
    __syncthreads();
    if (s_old != G_TOTAL - 1) return;

    // This is the last block: every other block's stores are globally visible
    // (each fenced before its arrival). Worklist is empty in practice.
    __threadfence();
    const int cnt = g_cnt;
    for (int m = 0; m < cnt; m++) {
        const int row = g_rows[m];
        const int b = row / L_DIM;
        const float sigma = (1.0f - EPS) / (1.0f - (1.0f - EPS) * t[b]);
        const float* __restrict__ orow = outp + (long long)row * V_DIM;
        float* __restrict__       rrow = rev  + (long long)row * V_DIM;

        float sum = 0.0f;
        for (int v = tid; v < V_DIM; v += 256) {
            if (v == mask_tok) continue;
            float s = expf(orow[v]);
            sum += s;
            rrow[v] = sigma * s;
        }
        s_sum[tid] = sum;
        __syncthreads();
        for (int off = 128; off > 0; off >>= 1) {
            if (tid < off) s_sum[tid] += s_sum[tid + off];
            __syncthreads();
        }
        if (tid == 0) rrow[mask_tok] = -sigma * s_sum[0];
        __syncthreads();
    }

    if (tid == 0) {          // reset for next graph replay (deterministic)
        g_cnt = 0;
        g_done = 0;
    }
}

extern "C" void kernel_launch(void* const* d_in, const int* in_sizes, int n_in,
                              void* d_out, int out_size) {
    const float* outp   = (const float*)d_in[0]; // [B,L,V] f32
    const int*   xt     = (const int*)  d_in[1]; // [B,L]   i32
    const float* t      = (const float*)d_in[2]; // [B]     f32
    const float* step_p = (const float*)d_in[3]; // scalar  f32
    const float* u      = (const float*)d_in[4]; // [B,L,V] f32

    float* x_new = (float*)d_out;                  // first B*L elements
    float* rev   = (float*)d_out + ROWS;           // then B*L*V elements

    fused_kernel<<<G_TOTAL, 256>>>(outp, xt, t, step_p, u, x_new, rev);
}

// round 8
// speedup vs baseline: 1.0234x; 1.0234x over previous
#include <cuda_runtime.h>
#include <math.h>

// Problem constants (fixed by the reference)
#define B_DIM 2
#define L_DIM 2048
#define V_DIM 32001
#define ROWS (B_DIM * L_DIM)                       // 4096
#define ROW_BYTES ((long long)V_DIM * 4)           // 128004
#define REV_FLOATS (131076096LL)                   // ROWS * V_DIM, divisible by 8
#define N8 (REV_FLOATS / 8)                        // 16384512 32-byte units

#define G_LOGIC 16                                 // logic blocks (4096 threads)
#define G_FILL 4096                                // fill blocks
#define G_TOTAL (G_LOGIC + G_FILL)
#define FILL_CHUNK ((N8 + G_FILL - 1) / G_FILL)    // 4001 F8 per block

struct alignas(32) F8 { float4 a, b; };

__device__ __forceinline__ float gumbel_noise(float u) {
    const float GEPS = 1e-6f;
    return GEPS - logf(GEPS + (1.0f - GEPS) * u);
}

__device__ __forceinline__ bool is_mask_tok(int x) {
    return x == -1 || x == (V_DIM - 1);
}

// Single launch, no cross-block protocol:
//   blocks [0, G_LOGIC): row logic. x_new for every row; masked rows get the
//     full SEDD reverse-rate + gumbel sample, INCLUDING direct rev-row writes.
//   blocks [G_LOGIC, G_TOTAL): flat 32B zero fill of rev, SKIPPING any bytes
//     that belong to a masked row (each ~128KB chunk overlaps at most 2 rows,
//     so two xt loads decide; with ~0 masked rows the fast path is taken
//     essentially always). No write conflict -> no fence/ordering needed.
__global__ __launch_bounds__(256)
void fused_kernel(const float* __restrict__ outp,   // [B,L,V]
                  const int* __restrict__ xt,       // [B,L]
                  const float* __restrict__ t,      // [B]
                  const float* __restrict__ step_p, // [1]
                  const float* __restrict__ u,      // [B,L,V]
                  float* __restrict__ x_new,        // [B*L]
                  float* __restrict__ rev)          // [B,L,V]
{
    const int tid = threadIdx.x;
    const int mask_tok = V_DIM - 1;
    const float EPS = 1e-3f;

    if (blockIdx.x >= G_LOGIC) {
        // ---- fill path ----
        const long long fb = blockIdx.x - G_LOGIC;
        const long long base = fb * FILL_CHUNK;
        long long end = base + FILL_CHUNK;
        if (end > N8) end = N8;
        if (base >= end) return;

        const long long byte0 = base * 32;
        const long long byte1 = end * 32;
        const int row0 = (int)(byte0 / ROW_BYTES);
        int row1 = (int)((byte1 - 1) / ROW_BYTES);
        if (row1 > ROWS - 1) row1 = ROWS - 1;

        const bool m0 = is_mask_tok(xt[row0]);
        const bool m1 = (row1 != row0) ? is_mask_tok(xt[row1]) : m0;

        if (!m0 && !m1) {
            // fast path: contiguous 32B stores over the whole chunk
            F8 z; z.a = make_float4(0.f, 0.f, 0.f, 0.f); z.b = z.a;
            F8* __restrict__ p = (F8*)rev;
            for (long long i = base + tid; i < end; i += 256) p[i] = z;
        } else {
            // rare path: elementwise, skipping floats owned by masked rows
            // (floats never straddle rows: ROW_BYTES % 4 == 0)
            const long long f0 = byte0 >> 2, f1 = byte1 >> 2;
            const long long rowsplit = (long long)(row0 + 1) * V_DIM; // first float of row0+1
            for (long long i = f0 + tid; i < f1; i += 256) {
                const bool masked = (i < rowsplit) ? m0 : m1;
                if (!masked) rev[i] = 0.0f;
            }
        }
        return;
    }

    // ---- row logic: thread-per-row ----
    const int row = blockIdx.x * 256 + tid;   // 0..4095

    __shared__ int s_count;
    __shared__ int s_rows[256];
    if (tid == 0) s_count = 0;
    __syncthreads();

    int x = xt[row];
    if (x == -1) x = mask_tok;

    if (x != mask_tok) {
        // rev row is exactly zero; argmax of xt_prob/gnoise is x itself.
        x_new[row] = (float)x;
    } else {
        int slot = atomicAdd(&s_count, 1);
        s_rows[slot] = row;
    }
    __syncthreads();

    const int cnt = s_count;
    if (cnt == 0) return;

    // ---- cooperative heavy path: full rev row + gumbel sample ----
    __shared__ float s_sum[256];
    __shared__ float s_val[256];
    __shared__ int   s_idx[256];

    const float step = *step_p;

    for (int m = 0; m < cnt; m++) {
        const int mrow = s_rows[m];
        const int b = mrow / L_DIM;
        const float sigma = (1.0f - EPS) / (1.0f - (1.0f - EPS) * t[b]);

        const float* __restrict__ orow = outp + (long long)mrow * V_DIM;
        const float* __restrict__ urow = u    + (long long)mrow * V_DIM;
        float* __restrict__       rrow = rev  + (long long)mrow * V_DIM;

        float sum = 0.0f;
        float best_v = -INFINITY;
        int   best_i = V_DIM;

        for (int v = tid; v < V_DIM; v += 256) {
            if (v == mask_tok) continue;
            float s = expf(orow[v]);
            sum += s;
            float r = sigma * s;          // off-diagonal rev_rate
            rrow[v] = r;                  // fill skips this row -> no race
            float g = gumbel_noise(urow[v]);
            float ratio = (step * r) / g;
            if (ratio > best_v || (ratio == best_v && v < best_i)) {
                best_v = ratio;
                best_i = v;
            }
        }

        s_sum[tid] = sum;
        s_val[tid] = best_v;
        s_idx[tid] = best_i;
        __syncthreads();

        for (int off = 128; off > 0; off >>= 1) {
            if (tid < off) {
                s_sum[tid] += s_sum[tid + off];
                float ov = s_val[tid + off];
                int   oi = s_idx[tid + off];
                if (ov > s_val[tid] || (ov == s_val[tid] && oi < s_idx[tid])) {
                    s_val[tid] = ov;
                    s_idx[tid] = oi;
                }
            }
            __syncthreads();
        }

        if (tid == 0) {
            float rd = sigma * (-s_sum[0]);        // diagonal rev_rate
            rrow[mask_tok] = rd;
            float prob = 1.0f + step * rd;         // oh=1 at diagonal
            float g = gumbel_noise(urow[mask_tok]);
            float ratio = prob / g;
            int res = s_idx[0];
            if (ratio > s_val[0]) res = mask_tok;  // tie -> lower index wins
            x_new[mrow] = (res == mask_tok) ? -1.0f : (float)res;
        }
        __syncthreads();
    }
}

extern "C" void kernel_launch(void* const* d_in, const int* in_sizes, int n_in,
                              void* d_out, int out_size) {
    const float* outp   = (const float*)d_in[0]; // [B,L,V] f32
    const int*   xt     = (const int*)  d_in[1]; // [B,L]   i32
    const float* t      = (const float*)d_in[2]; // [B]     f32
    const float* step_p = (const float*)d_in[3]; // scalar  f32
    const float* u      = (const float*)d_in[4]; // [B,L,V] f32

    float* x_new = (float*)d_out;                  // first B*L elements
    float* rev   = (float*)d_out + ROWS;           // then B*L*V elements

    fused_kernel<<<G_TOTAL, 256>>>(outp, xt, t, step_p, u, x_new, rev);
}

// round 9
// speedup vs baseline: 1.0286x; 1.0050x over previous
#include <cuda_runtime.h>
#include <math.h>

// Problem constants (fixed by the reference)
#define B_DIM 2
#define L_DIM 2048
#define V_DIM 32001
#define ROWS (B_DIM * L_DIM)                       // 4096
#define ROW_BYTES ((long long)V_DIM * 4)           // 128004
#define REV_FLOATS (131076096LL)                   // ROWS * V_DIM, divisible by 8
#define N8 (REV_FLOATS / 8)                        // 16384512 32-byte units

#define G_LOGIC 16                                 // logic blocks (4096 threads)
#define G_FILL 4096                                // fill blocks
#define G_TOTAL (G_LOGIC + G_FILL)
// Chunk size in 32B units, rounded UP to a multiple of 4 (=128B) so every
// chunk starts 128B-line-aligned: 4004*32 = 128128, 128128 % 128 == 0.
// 4096 * 4004 = 16400384 >= N8, so trailing blocks clamp/idle.
#define FILL_CHUNK 4004LL

struct alignas(32) F8 { float4 a, b; };

__device__ __forceinline__ float gumbel_noise(float u) {
    const float GEPS = 1e-6f;
    return GEPS - logf(GEPS + (1.0f - GEPS) * u);
}

__device__ __forceinline__ bool is_mask_tok(int x) {
    return x == -1 || x == (V_DIM - 1);
}

// Single launch, no cross-block protocol:
//   blocks [0, G_LOGIC): row logic. x_new for every row; masked rows get the
//     full SEDD reverse-rate + gumbel sample, INCLUDING direct rev-row writes.
//   blocks [G_LOGIC, G_TOTAL): flat, 128B-aligned zero fill of rev, SKIPPING
//     bytes of masked rows (each ~128KB chunk overlaps at most 2 rows; two xt
//     loads decide; with ~0 masked rows the fast path runs always).
__global__ __launch_bounds__(256)
void fused_kernel(const float* __restrict__ outp,   // [B,L,V]
                  const int* __restrict__ xt,       // [B,L]
                  const float* __restrict__ t,      // [B]
                  const float* __restrict__ step_p, // [1]
                  const float* __restrict__ u,      // [B,L,V]
                  float* __restrict__ x_new,        // [B*L]
                  float* __restrict__ rev)          // [B,L,V]
{
    const int tid = threadIdx.x;
    const int mask_tok = V_DIM - 1;
    const float EPS = 1e-3f;

    if (blockIdx.x >= G_LOGIC) {
        // ---- fill path: 128B-aligned contiguous chunk per block ----
        const long long fb = blockIdx.x - G_LOGIC;
        const long long base = fb * FILL_CHUNK;
        long long end = base + FILL_CHUNK;
        if (end > N8) end = N8;
        if (base >= end) return;

        const long long byte0 = base * 32;
        const long long byte1 = end * 32;
        const int row0 = (int)(byte0 / ROW_BYTES);
        int row1 = (int)((byte1 - 1) / ROW_BYTES);
        if (row1 > ROWS - 1) row1 = ROWS - 1;

        const bool m0 = is_mask_tok(xt[row0]);
        const bool m1 = (row1 != row0) ? is_mask_tok(xt[row1]) : m0;

        if (!m0 && !m1) {
            // fast path: contiguous 32B stores, all warp segments line-aligned
            F8 z; z.a = make_float4(0.f, 0.f, 0.f, 0.f); z.b = z.a;
            F8* __restrict__ p = (F8*)rev;
            for (long long i = base + tid; i < end; i += 256) p[i] = z;
        } else {
            // rare path: elementwise, skipping floats owned by masked rows
            // (floats never straddle rows: ROW_BYTES % 4 == 0)
            const long long f0 = byte0 >> 2, f1 = byte1 >> 2;
            const long long rowsplit = (long long)(row0 + 1) * V_DIM;
            for (long long i = f0 + tid; i < f1; i += 256) {
                const bool masked = (i < rowsplit) ? m0 : m1;
                if (!masked) rev[i] = 0.0f;
            }
        }
        return;
    }

    // ---- row logic: thread-per-row ----
    const int row = blockIdx.x * 256 + tid;   // 0..4095

    __shared__ int s_count;
    __shared__ int s_rows[256];
    if (tid == 0) s_count = 0;
    __syncthreads();

    int x = xt[row];
    if (x == -1) x = mask_tok;

    if (x != mask_tok) {
        // rev row is exactly zero; argmax of xt_prob/gnoise is x itself.
        x_new[row] = (float)x;
    } else {
        int slot = atomicAdd(&s_count, 1);
        s_rows[slot] = row;
    }
    __syncthreads();

    const int cnt = s_count;
    if (cnt == 0) return;

    // ---- cooperative heavy path: full rev row + gumbel sample ----
    __shared__ float s_sum[256];
    __shared__ float s_val[256];
    __shared__ int   s_idx[256];

    const float step = *step_p;

    for (int m = 0; m < cnt; m++) {
        const int mrow = s_rows[m];
        const int b = mrow / L_DIM;
        const float sigma = (1.0f - EPS) / (1.0f - (1.0f - EPS) * t[b]);

        const float* __restrict__ orow = outp + (long long)mrow * V_DIM;
        const float* __restrict__ urow = u    + (long long)mrow * V_DIM;
        float* __restrict__       rrow = rev  + (long long)mrow * V_DIM;

        float sum = 0.0f;
        float best_v = -INFINITY;
        int   best_i = V_DIM;

        for (int v = tid; v < V_DIM; v += 256) {
            if (v == mask_tok) continue;
            float s = expf(orow[v]);
            sum += s;
            float r = sigma * s;          // off-diagonal rev_rate
            rrow[v] = r;                  // fill skips this row -> no race
            float g = gumbel_noise(urow[v]);
            float ratio = (step * r) / g;
            if (ratio > best_v || (ratio == best_v && v < best_i)) {
                best_v = ratio;
                best_i = v;
            }
        }

        s_sum[tid] = sum;
        s_val[tid] = best_v;
        s_idx[tid] = best_i;
        __syncthreads();

        for (int off = 128; off > 0; off >>= 1) {
            if (tid < off) {
                s_sum[tid] += s_sum[tid + off];
                float ov = s_val[tid + off];
                int   oi = s_idx[tid + off];
                if (ov > s_val[tid] || (ov == s_val[tid] && oi < s_idx[tid])) {
                    s_val[tid] = ov;
                    s_idx[tid] = oi;
                }
            }
            __syncthreads();
        }

        if (tid == 0) {
            float rd = sigma * (-s_sum[0]);        // diagonal rev_rate
            rrow[mask_tok] = rd;
            float prob = 1.0f + step * rd;         // oh=1 at diagonal
            float g = gumbel_noise(urow[mask_tok]);
            float ratio = prob / g;
            int res = s_idx[0];
            if (ratio > s_val[0]) res = mask_tok;  // tie -> lower index wins
            x_new[mrow] = (res == mask_tok) ? -1.0f : (float)res;
        }
        __syncthreads();
    }
}

extern "C" void kernel_launch(void* const* d_in, const int* in_sizes, int n_in,
                              void* d_out, int out_size) {
    const float* outp   = (const float*)d_in[0]; // [B,L,V] f32
    const int*   xt     = (const int*)  d_in[1]; // [B,L]   i32
    const float* t      = (const float*)d_in[2]; // [B]     f32
    const float* step_p = (const float*)d_in[3]; // scalar  f32
    const float* u      = (const float*)d_in[4]; // [B,L,V] f32

    float* x_new = (float*)d_out;                  // first B*L elements
    float* rev   = (float*)d_out + ROWS;           // then B*L*V elements

    fused_kernel<<<G_TOTAL, 256>>>(outp, xt, t, step_p, u, x_new, rev);
}